// round 2
// baseline (speedup 1.0000x reference)
#include <cuda_runtime.h>
#include <math.h>

#define NUM_DST   10000
#define NUM_EDGES 600000
#define DN  100
#define DE  172
#define DT_ 100
#define DIN 372      // DN + DE + DT
#define DOUT 128
#define NCOLS 256    // K(128) | V(128)

// ---------------- scratch (static __device__, allowed) ----------------
__device__ float    g_Q[NUM_DST * DOUT];        // q_nodes
__device__ float    g_V[(size_t)NUM_EDGES * DOUT];
__device__ float    g_score[NUM_EDGES * 2];     // scores, then exp(s-m)
__device__ unsigned g_segMax[NUM_DST * 2];      // ordered-uint float keys
__device__ float    g_segSum[NUM_DST * 2];      // sum of exp, then 1/sum
__device__ float    g_agg[NUM_DST * DOUT];
__device__ float    g_ab[2];                    // per-head sum of att_bias

// ---------------- init ----------------
__global__ void k_init(const float* __restrict__ att_bias) {
    int idx = blockIdx.x * blockDim.x + threadIdx.x;
    int stride = gridDim.x * blockDim.x;
    for (int i = idx; i < NUM_DST * DOUT; i += stride) g_agg[i] = 0.f;
    for (int i = idx; i < NUM_DST * 2; i += stride) { g_segMax[i] = 0u; g_segSum[i] = 0.f; }
    if (idx < 2) {
        float s = 0.f;
        for (int d = 0; d < 64; ++d) s += att_bias[idx * 64 + d];
        g_ab[idx] = s;
    }
}

// ---------------- Q = [h_dst | cos(time_b)] @ wq + bq ----------------
__global__ void k_qnodes(const float* __restrict__ h, const float* __restrict__ time_b,
                         const float* __restrict__ wq, const float* __restrict__ bq) {
    __shared__ float xs[8][DN];
    __shared__ float costb[DT_];
    int node0 = blockIdx.x * 8;
    int j = threadIdx.x;                       // 0..127 = output col
    if (j < DT_) costb[j] = cosf(time_b[j]);
    for (int idx = j; idx < 8 * DN; idx += 128) {
        int n = idx / DN, i = idx % DN;
        xs[n][i] = h[(node0 + n) * DN + i];
    }
    __syncthreads();
    // time-feature contribution is identical for every node
    float cacc = bq[j];
    for (int i = 0; i < DT_; ++i) cacc += costb[i] * wq[(DN + i) * DOUT + j];
    float acc[8];
#pragma unroll
    for (int n = 0; n < 8; ++n) acc[n] = cacc;
    for (int i = 0; i < DN; ++i) {
        float w = wq[i * DOUT + j];
#pragma unroll
        for (int n = 0; n < 8; ++n) acc[n] = fmaf(xs[n][i], w, acc[n]);
    }
#pragma unroll
    for (int n = 0; n < 8; ++n) g_Q[(node0 + n) * DOUT + j] = acc[n];
}

// ---------------- edge K/V GEMM + scores (THE hot kernel) ----------------
// Block: 256 threads, tile = 64 edges x 256 cols (K|V), 8x8 microtile/thread.
// warp = tid/32 owns edges [warp*8, warp*8+8); lane owns cols [lane*8, lane*8+8).
__global__ void __launch_bounds__(256) k_edges(
    const float* __restrict__ h,  const float* __restrict__ ef,
    const float* __restrict__ dt, const int*   __restrict__ dst_idx,
    const float* __restrict__ time_w, const float* __restrict__ time_b,
    const float* __restrict__ wk, const float* __restrict__ bk,
    const float* __restrict__ wv, const float* __restrict__ bv) {
    __shared__ float Xs[32][65];     // [k][edge], pad 65 -> conflict-free
    __shared__ float Ws[32][NCOLS];  // [k][col]
    const int tid  = threadIdx.x;
    const int lane = tid & 31;
    const int warp = tid >> 5;
    const int e0   = blockIdx.x * 64;
    const int col0 = lane * 8;

    float acc[8][8];
    {
        float bias[8];
#pragma unroll
        for (int c = 0; c < 8; ++c) {
            int col = col0 + c;
            bias[c] = (col < DOUT) ? bk[col] : bv[col - DOUT];
        }
#pragma unroll
        for (int j = 0; j < 8; ++j)
#pragma unroll
            for (int c = 0; c < 8; ++c) acc[j][c] = bias[c];
    }

    for (int k0 = 0; k0 < DIN; k0 += 32) {
        // generate X tile (transposed): 64 edges x 32 feature dims
#pragma unroll
        for (int r = 0; r < 8; ++r) {
            int linear = r * 256 + tid;
            int ee = linear >> 5;
            int il = linear & 31;
            int i  = k0 + il;
            int e  = e0 + ee;
            float v = 0.f;
            if (i < DN)            v = h[(size_t)(NUM_DST + e) * DN + i];
            else if (i < DN + DE)  v = ef[(size_t)e * DE + (i - DN)];
            else if (i < DIN) {
                int ti = i - DN - DE;
                v = __cosf(dt[e] * time_w[ti] + time_b[ti]);
            }
            Xs[il][ee] = v;
        }
        // load W tile: col = tid, rows 0..31 (coalesced)
        {
            int col = tid;
#pragma unroll
            for (int rr = 0; rr < 32; ++rr) {
                int i = k0 + rr;
                float w = 0.f;
                if (i < DIN) w = (col < DOUT) ? wk[i * DOUT + col]
                                              : wv[i * DOUT + (col - DOUT)];
                Ws[rr][col] = w;
            }
        }
        __syncthreads();
#pragma unroll 8
        for (int kk = 0; kk < 32; ++kk) {
            float a[8];
#pragma unroll
            for (int j = 0; j < 8; ++j) a[j] = Xs[kk][warp * 8 + j];   // broadcast
            float4 b0 = *(const float4*)&Ws[kk][col0];
            float4 b1 = *(const float4*)&Ws[kk][col0 + 4];
            float b[8] = {b0.x, b0.y, b0.z, b0.w, b1.x, b1.y, b1.z, b1.w};
#pragma unroll
            for (int j = 0; j < 8; ++j)
#pragma unroll
                for (int c = 0; c < 8; ++c)
                    acc[j][c] = fmaf(a[j], b[c], acc[j][c]);
        }
        __syncthreads();
    }

    // epilogue: V store + fused Q.K score + leaky-relu + segment-max
    float ab = g_ab[(lane >= 8) ? 1 : 0];
#pragma unroll
    for (int j = 0; j < 8; ++j) {
        int e   = e0 + warp * 8 + j;
        int dst = dst_idx[e];
        if (lane >= 16) {
            float* vp = &g_V[(size_t)e * DOUT + (lane - 16) * 8];
            *(float4*)vp       = make_float4(acc[j][0], acc[j][1], acc[j][2], acc[j][3]);
            *(float4*)(vp + 4) = make_float4(acc[j][4], acc[j][5], acc[j][6], acc[j][7]);
        }
        float p = 0.f;
        if (lane < 16) {
            const float* q = &g_Q[dst * DOUT + col0];
#pragma unroll
            for (int c = 0; c < 8; ++c) p = fmaf(acc[j][c], q[c], p);
        }
        p += __shfl_down_sync(0xffffffffu, p, 4, 8);
        p += __shfl_down_sync(0xffffffffu, p, 2, 8);
        p += __shfl_down_sync(0xffffffffu, p, 1, 8);
        if (lane == 0 || lane == 8) {
            int head = lane >> 3;
            float s = p + ab;
            s = (s > 0.f) ? s : 0.2f * s;          // leaky_relu(0.2)
            g_score[e * 2 + head] = s;
            int si = __float_as_int(s);
            unsigned key = (unsigned)(si ^ ((si >> 31) | 0x80000000));
            atomicMax(&g_segMax[dst * 2 + head], key);
        }
    }
}

// ---------------- exp(s - m) + segment sum ----------------
__global__ void k_expsum(const int* __restrict__ dst_idx) {
    int idx = blockIdx.x * blockDim.x + threadIdx.x;
    if (idx >= NUM_EDGES * 2) return;
    int e = idx >> 1, head = idx & 1;
    int dst = dst_idx[e];
    unsigned k = g_segMax[dst * 2 + head];
    int mi = (k & 0x80000000u) ? (int)(k ^ 0x80000000u) : (int)~k;
    float m = __int_as_float(mi);
    float ex = __expf(g_score[idx] - m);
    g_score[idx] = ex;
    atomicAdd(&g_segSum[dst * 2 + head], ex);
}

// ---------------- 1/z (avoids 77M divisions in aggregate) ----------------
__global__ void k_invz() {
    int i = blockIdx.x * blockDim.x + threadIdx.x;
    if (i >= NUM_DST * 2) return;
    float z = g_segSum[i];
    g_segSum[i] = (z > 0.f) ? 1.f / z : 0.f;
}

// ---------------- agg += att * V ----------------
__global__ void k_aggregate(const int* __restrict__ dst_idx) {
    size_t idx = (size_t)blockIdx.x * blockDim.x + threadIdx.x;
    int e = (int)(idx >> 7);
    int c = (int)(idx & 127);
    if (e >= NUM_EDGES) return;
    int dst = dst_idx[e];
    int head = c >> 6;
    float att = g_score[e * 2 + head] * g_segSum[dst * 2 + head];
    float v   = g_V[(size_t)e * DOUT + c] * att;
    atomicAdd(&g_agg[dst * DOUT + c], v);
}

// ---------------- out = LN(relu([agg | h_dst] @ wout + bout)) ----------------
__global__ void k_out(const float* __restrict__ h, const float* __restrict__ wout,
                      const float* __restrict__ bout, const float* __restrict__ ln_g,
                      const float* __restrict__ ln_b, float* __restrict__ out) {
    __shared__ float xs[8][DOUT + DN];   // 228
    __shared__ float rst[8][DOUT];
    int node0 = blockIdx.x * 8;
    int j = threadIdx.x;                 // 0..127
    for (int idx = j; idx < 8 * DOUT; idx += 128) {
        int n = idx >> 7, i = idx & 127;
        xs[n][i] = g_agg[(node0 + n) * DOUT + i];
    }
    for (int idx = j; idx < 8 * DN; idx += 128) {
        int n = idx / DN, i = idx % DN;
        xs[n][DOUT + i] = h[(node0 + n) * DN + i];
    }
    __syncthreads();
    float b0 = bout[j];
    float acc[8];
#pragma unroll
    for (int n = 0; n < 8; ++n) acc[n] = b0;
    for (int i = 0; i < DOUT + DN; ++i) {
        float w = wout[i * DOUT + j];
#pragma unroll
        for (int n = 0; n < 8; ++n) acc[n] = fmaf(xs[n][i], w, acc[n]);
    }
#pragma unroll
    for (int n = 0; n < 8; ++n) rst[n][j] = fmaxf(acc[n], 0.f);
    __syncthreads();
    int warp = j >> 5, lane = j & 31;
#pragma unroll
    for (int t = 0; t < 2; ++t) {
        int n = warp * 2 + t;
        float s = 0.f, s2 = 0.f;
#pragma unroll
        for (int c = lane; c < DOUT; c += 32) { float v = rst[n][c]; s += v; s2 += v * v; }
#pragma unroll
        for (int o = 16; o > 0; o >>= 1) {
            s  += __shfl_xor_sync(0xffffffffu, s, o);
            s2 += __shfl_xor_sync(0xffffffffu, s2, o);
        }
        float mu   = s * (1.f / DOUT);
        float var  = s2 * (1.f / DOUT) - mu * mu;
        float rstd = rsqrtf(var + 1e-5f);
#pragma unroll
        for (int c = lane; c < DOUT; c += 32) {
            out[(size_t)(node0 + n) * DOUT + c] =
                (rst[n][c] - mu) * rstd * ln_g[c] + ln_b[c];
        }
    }
}

// ---------------- launch ----------------
extern "C" void kernel_launch(void* const* d_in, const int* in_sizes, int n_in,
                              void* d_out, int out_size) {
    // inputs: h, ef, dt, dst_idx, [num_dst], time_w, time_b, wq, bq, wk, bk,
    //         wv, bv, att_bias, wout, bout, ln_g, ln_b
    int base = (in_sizes[4] == 1) ? 5 : 4;   // skip scalar num_dst if present
    const float* h        = (const float*)d_in[0];
    const float* ef       = (const float*)d_in[1];
    const float* dt       = (const float*)d_in[2];
    const int*   dst_idx  = (const int*)  d_in[3];
    const float* time_w   = (const float*)d_in[base + 0];
    const float* time_b   = (const float*)d_in[base + 1];
    const float* wq       = (const float*)d_in[base + 2];
    const float* bq       = (const float*)d_in[base + 3];
    const float* wk       = (const float*)d_in[base + 4];
    const float* bk       = (const float*)d_in[base + 5];
    const float* wv       = (const float*)d_in[base + 6];
    const float* bv       = (const float*)d_in[base + 7];
    const float* att_bias = (const float*)d_in[base + 8];
    const float* wout     = (const float*)d_in[base + 9];
    const float* bout     = (const float*)d_in[base + 10];
    const float* ln_g     = (const float*)d_in[base + 11];
    const float* ln_b     = (const float*)d_in[base + 12];
    float* out = (float*)d_out;

    k_init<<<1280, 256>>>(att_bias);
    k_qnodes<<<NUM_DST / 8, 128>>>(h, time_b, wq, bq);
    k_edges<<<NUM_EDGES / 64, 256>>>(h, ef, dt, dst_idx, time_w, time_b, wk, bk, wv, bv);
    k_expsum<<<(NUM_EDGES * 2 + 255) / 256, 256>>>(dst_idx);
    k_invz<<<(NUM_DST * 2 + 255) / 256, 256>>>();
    k_aggregate<<<(int)(((size_t)NUM_EDGES * DOUT) / 256), 256>>>(dst_idx);
    k_out<<<NUM_DST / 8, 128>>>(h, wout, bout, ln_g, ln_b, out);
}

// round 3
// speedup vs baseline: 14.8846x; 14.8846x over previous
#include <cuda_runtime.h>
#include <math.h>

#define NUM_DST   10000
#define NUM_EDGES 600000
#define DN  100
#define DE  172
#define DT_ 100
#define FPH 372      // features per edge = DN+DE+DT
#define DOUT 128
#define UPD 744      // 2 heads * 372

// ---------------- scratch ----------------
__device__ float g_Q[NUM_DST * DOUT];
__device__ float g_qc[NUM_DST * 2];            // Q_h . bk_h
__device__ float g_u[(size_t)NUM_DST * UPD];   // wk_h @ Q_h per dst
__device__ float g_S[(size_t)NUM_DST * UPD];   // att-weighted feature sums
__device__ float g_attsum[NUM_DST * 2];        // 1 if deg>0 else 0
__device__ float g_agg[NUM_DST * DOUT];
__device__ float g_ab[2];                      // per-head sum of att_bias
__device__ int   g_hist[NUM_DST];
__device__ int   g_rowptr[NUM_DST + 1];
__device__ int   g_cursor[NUM_DST];
__device__ int   g_csr[NUM_EDGES];

// ---------------- init: zero hist + att_bias head sums ----------------
__global__ void k_init(const float* __restrict__ att_bias) {
    int i = blockIdx.x * blockDim.x + threadIdx.x;
    if (i < NUM_DST) g_hist[i] = 0;
    if (i < 2) {
        float s = 0.f;
        for (int d = 0; d < 64; ++d) s += att_bias[i * 64 + d];
        g_ab[i] = s;
    }
}

// ---------------- Q = [h_dst | cos(time_b)] @ wq + bq ----------------
__global__ void k_qnodes(const float* __restrict__ h, const float* __restrict__ time_b,
                         const float* __restrict__ wq, const float* __restrict__ bq) {
    __shared__ float xs[8][DN];
    __shared__ float costb[DT_];
    int node0 = blockIdx.x * 8;
    int j = threadIdx.x;                       // 0..127 = output col
    if (j < DT_) costb[j] = cosf(time_b[j]);
    for (int idx = j; idx < 8 * DN; idx += 128) {
        int n = idx / DN, i = idx % DN;
        xs[n][i] = h[(node0 + n) * DN + i];
    }
    __syncthreads();
    float cacc = bq[j];
    for (int i = 0; i < DT_; ++i) cacc += costb[i] * wq[(DN + i) * DOUT + j];
    float acc[8];
#pragma unroll
    for (int n = 0; n < 8; ++n) acc[n] = cacc;
    for (int i = 0; i < DN; ++i) {
        float w = wq[i * DOUT + j];
#pragma unroll
        for (int n = 0; n < 8; ++n) acc[n] = fmaf(xs[n][i], w, acc[n]);
    }
#pragma unroll
    for (int n = 0; n < 8; ++n) g_Q[(node0 + n) * DOUT + j] = acc[n];
}

// ---------------- qc[dst][h] = Q_h[dst] . bk_h ----------------
__global__ void k_qb(const float* __restrict__ bk) {
    int idx  = blockIdx.x * 4 + (threadIdx.x >> 5);
    int lane = threadIdx.x & 31;
    if (idx >= NUM_DST * 2) return;
    int dst = idx >> 1, hh = idx & 1;
    const float* q = &g_Q[dst * DOUT + hh * 64];
    const float* b = &bk[hh * 64];
    float v = q[lane] * b[lane] + q[lane + 32] * b[lane + 32];
#pragma unroll
    for (int off = 16; off > 0; off >>= 1) v += __shfl_xor_sync(0xffffffffu, v, off);
    if (lane == 0) g_qc[idx] = v;
}

// ---------------- u[dst][h][i] = sum_d wk[i, h*64+d] * Q[dst, h*64+d] ----------------
__global__ void k_u(const float* __restrict__ wk) {
    __shared__ float Qs[8][DOUT];
    int d0 = blockIdx.x * 8;
    int j  = threadIdx.x;                       // 0..127
    for (int idx = j; idx < 8 * DOUT; idx += 128)
        Qs[idx >> 7][idx & 127] = g_Q[(d0 + (idx >> 7)) * DOUT + (idx & 127)];
    __syncthreads();
    int i = blockIdx.y * 124 + j;               // feature row, 3*124 = 372
    if (j >= 124) return;
#pragma unroll
    for (int hh = 0; hh < 2; ++hh) {
        float acc[8];
#pragma unroll
        for (int n = 0; n < 8; ++n) acc[n] = 0.f;
        for (int d = 0; d < 64; ++d) {
            float w = wk[i * DOUT + hh * 64 + d];
#pragma unroll
            for (int n = 0; n < 8; ++n) acc[n] = fmaf(w, Qs[n][hh * 64 + d], acc[n]);
        }
#pragma unroll
        for (int n = 0; n < 8; ++n)
            g_u[(size_t)(d0 + n) * UPD + hh * FPH + i] = acc[n];
    }
}

// ---------------- CSR build ----------------
__global__ void k_hist(const int* __restrict__ dst_idx) {
    int e = blockIdx.x * blockDim.x + threadIdx.x;
    if (e < NUM_EDGES) atomicAdd(&g_hist[dst_idx[e]], 1);
}

__global__ void k_scan() {      // single block, 1024 threads, 10 dsts/thread
    __shared__ int wsum[32];
    int t = threadIdx.x, lane = t & 31, wid = t >> 5;
    int base = t * 10;
    int loc[10]; int s = 0;
#pragma unroll
    for (int r = 0; r < 10; ++r) {
        int i = base + r;
        int c = (i < NUM_DST) ? g_hist[i] : 0;
        loc[r] = s; s += c;
    }
    int v = s;
#pragma unroll
    for (int off = 1; off < 32; off <<= 1) {
        int n = __shfl_up_sync(0xffffffffu, v, off);
        if (lane >= off) v += n;
    }
    if (lane == 31) wsum[wid] = v;
    __syncthreads();
    if (wid == 0) {
        int wv = wsum[lane];
#pragma unroll
        for (int off = 1; off < 32; off <<= 1) {
            int n = __shfl_up_sync(0xffffffffu, wv, off);
            if (lane >= off) wv += n;
        }
        wsum[lane] = wv;   // inclusive scan of warp totals
    }
    __syncthreads();
    int warpbase = (wid == 0) ? 0 : wsum[wid - 1];
    int tbase = warpbase + (v - s);   // exclusive prefix for this thread
#pragma unroll
    for (int r = 0; r < 10; ++r) {
        int i = base + r;
        if (i < NUM_DST) { int p = tbase + loc[r]; g_rowptr[i] = p; g_cursor[i] = p; }
    }
    if (t == 0) g_rowptr[NUM_DST] = NUM_EDGES;
}

__global__ void k_scatter(const int* __restrict__ dst_idx) {
    int e = blockIdx.x * blockDim.x + threadIdx.x;
    if (e >= NUM_EDGES) return;
    int pos = atomicAdd(&g_cursor[dst_idx[e]], 1);
    g_csr[pos] = e;
}

// ---------------- fused: scores + segment softmax + weighted feature sum ----------------
// one block (128 thr, 4 warps) per dst; warp-level online softmax, merged at end.
__global__ void __launch_bounds__(128) k_fused(
    const float* __restrict__ h,  const float* __restrict__ ef,
    const float* __restrict__ dtp,
    const float* __restrict__ time_w, const float* __restrict__ time_b) {
    __shared__ float tw[DT_], tb[DT_];
    __shared__ float Ss[4][UPD];
    __shared__ float sm_m[4][2], sm_z[4][2];
    int dst  = blockIdx.x;
    int tid  = threadIdx.x, lane = tid & 31, warp = tid >> 5;
    int start = g_rowptr[dst], end = g_rowptr[dst + 1];
    if (start == end) {      // empty segment
        for (int idx = tid; idx < UPD; idx += 128) g_S[(size_t)dst * UPD + idx] = 0.f;
        if (tid < 2) g_attsum[dst * 2 + tid] = 0.f;
        return;
    }
    if (tid < DT_) { tw[tid] = time_w[tid]; tb[tid] = time_b[tid]; }

    float ur0[12], ur1[12];
#pragma unroll
    for (int k = 0; k < 12; ++k) {
        int f = lane + 32 * k;
        ur0[k] = (f < FPH) ? g_u[(size_t)dst * UPD + f]       : 0.f;
        ur1[k] = (f < FPH) ? g_u[(size_t)dst * UPD + FPH + f] : 0.f;
    }
    float c0 = g_qc[dst * 2 + 0] + g_ab[0];
    float c1 = g_qc[dst * 2 + 1] + g_ab[1];
    __syncthreads();

    float m0 = -1e30f, m1 = -1e30f, z0 = 0.f, z1 = 0.f;
    float S0[12], S1[12];
#pragma unroll
    for (int k = 0; k < 12; ++k) { S0[k] = 0.f; S1[k] = 0.f; }

    for (int pos = start + warp; pos < end; pos += 4) {
        int   eid = g_csr[pos];
        float dtv = dtp[eid];
        float x[12];
#pragma unroll
        for (int k = 0; k < 12; ++k) {
            int f = lane + 32 * k;
            float v;
            if (f < DN)            v = h[(size_t)(NUM_DST + eid) * DN + f];
            else if (f < DN + DE)  v = ef[(size_t)eid * DE + (f - DN)];
            else if (f < FPH) {
                int ti = f - (DN + DE);
                v = __cosf(dtv * tw[ti] + tb[ti]);
            } else v = 0.f;
            x[k] = v;
        }
        float p0 = 0.f, p1 = 0.f;
#pragma unroll
        for (int k = 0; k < 12; ++k) {
            p0 = fmaf(x[k], ur0[k], p0);
            p1 = fmaf(x[k], ur1[k], p1);
        }
#pragma unroll
        for (int off = 16; off > 0; off >>= 1) {
            p0 += __shfl_xor_sync(0xffffffffu, p0, off);
            p1 += __shfl_xor_sync(0xffffffffu, p1, off);
        }
        float s0 = p0 + c0; s0 = (s0 > 0.f) ? s0 : 0.2f * s0;  // leaky_relu
        float s1 = p1 + c1; s1 = (s1 > 0.f) ? s1 : 0.2f * s1;
        // online softmax accumulation, head 0
        if (s0 > m0) {
            float sc = __expf(m0 - s0);
            z0 = fmaf(z0, sc, 1.f);
#pragma unroll
            for (int k = 0; k < 12; ++k) S0[k] = fmaf(S0[k], sc, x[k]);
            m0 = s0;
        } else {
            float e = __expf(s0 - m0);
            z0 += e;
#pragma unroll
            for (int k = 0; k < 12; ++k) S0[k] = fmaf(e, x[k], S0[k]);
        }
        // head 1
        if (s1 > m1) {
            float sc = __expf(m1 - s1);
            z1 = fmaf(z1, sc, 1.f);
#pragma unroll
            for (int k = 0; k < 12; ++k) S1[k] = fmaf(S1[k], sc, x[k]);
            m1 = s1;
        } else {
            float e = __expf(s1 - m1);
            z1 += e;
#pragma unroll
            for (int k = 0; k < 12; ++k) S1[k] = fmaf(e, x[k], S1[k]);
        }
    }

    // merge warp partials
#pragma unroll
    for (int k = 0; k < 12; ++k) {
        int f = lane + 32 * k;
        if (f < FPH) { Ss[warp][f] = S0[k]; Ss[warp][FPH + f] = S1[k]; }
    }
    if (lane == 0) {
        sm_m[warp][0] = m0; sm_m[warp][1] = m1;
        sm_z[warp][0] = z0; sm_z[warp][1] = z1;
    }
    __syncthreads();
    float gm0 = -1e30f, gm1 = -1e30f;
#pragma unroll
    for (int w = 0; w < 4; ++w) {
        gm0 = fmaxf(gm0, sm_m[w][0]);
        gm1 = fmaxf(gm1, sm_m[w][1]);
    }
    float ew0[4], ew1[4], gz0 = 0.f, gz1 = 0.f;
#pragma unroll
    for (int w = 0; w < 4; ++w) {
        ew0[w] = __expf(sm_m[w][0] - gm0); gz0 = fmaf(sm_z[w][0], ew0[w], gz0);
        ew1[w] = __expf(sm_m[w][1] - gm1); gz1 = fmaf(sm_z[w][1], ew1[w], gz1);
    }
    float inv0 = 1.f / gz0, inv1 = 1.f / gz1;
    for (int f = tid; f < FPH; f += 128) {
        float a0 = 0.f, a1 = 0.f;
#pragma unroll
        for (int w = 0; w < 4; ++w) {
            a0 = fmaf(Ss[w][f],       ew0[w], a0);
            a1 = fmaf(Ss[w][FPH + f], ew1[w], a1);
        }
        g_S[(size_t)dst * UPD + f]       = a0 * inv0;
        g_S[(size_t)dst * UPD + FPH + f] = a1 * inv1;
    }
    if (tid < 2) g_attsum[dst * 2 + tid] = 1.f;
}

// ---------------- agg[dst,c] = S_h(c)[dst] . wv[:,c] + bv_c * attsum ----------------
__global__ void k_sv(const float* __restrict__ wv, const float* __restrict__ bv) {
    __shared__ float Ssm[8][UPD];
    __shared__ float asum[8][2];
    int n0 = blockIdx.x * 8;
    int j  = threadIdx.x;                       // 0..127 = output col
    for (int idx = j; idx < 8 * UPD; idx += 128) {
        int n = idx / UPD, i = idx % UPD;
        Ssm[n][i] = g_S[(size_t)(n0 + n) * UPD + i];
    }
    if (j < 16) asum[j >> 1][j & 1] = g_attsum[(n0 + (j >> 1)) * 2 + (j & 1)];
    __syncthreads();
    int hh = j >> 6;
    float bvj = bv[j];
    float acc[8];
#pragma unroll
    for (int n = 0; n < 8; ++n) acc[n] = bvj * asum[n][hh];
    for (int i = 0; i < FPH; ++i) {
        float w = wv[i * DOUT + j];
#pragma unroll
        for (int n = 0; n < 8; ++n) acc[n] = fmaf(Ssm[n][hh * FPH + i], w, acc[n]);
    }
#pragma unroll
    for (int n = 0; n < 8; ++n) g_agg[(n0 + n) * DOUT + j] = acc[n];
}

// ---------------- out = LN(relu([agg | h_dst] @ wout + bout)) ----------------
__global__ void k_out(const float* __restrict__ h, const float* __restrict__ wout,
                      const float* __restrict__ bout, const float* __restrict__ ln_g,
                      const float* __restrict__ ln_b, float* __restrict__ out) {
    __shared__ float xs[8][DOUT + DN];
    __shared__ float rst[8][DOUT];
    int node0 = blockIdx.x * 8;
    int j = threadIdx.x;
    for (int idx = j; idx < 8 * DOUT; idx += 128) {
        int n = idx >> 7, i = idx & 127;
        xs[n][i] = g_agg[(node0 + n) * DOUT + i];
    }
    for (int idx = j; idx < 8 * DN; idx += 128) {
        int n = idx / DN, i = idx % DN;
        xs[n][DOUT + i] = h[(node0 + n) * DN + i];
    }
    __syncthreads();
    float b0 = bout[j];
    float acc[8];
#pragma unroll
    for (int n = 0; n < 8; ++n) acc[n] = b0;
    for (int i = 0; i < DOUT + DN; ++i) {
        float w = wout[i * DOUT + j];
#pragma unroll
        for (int n = 0; n < 8; ++n) acc[n] = fmaf(xs[n][i], w, acc[n]);
    }
#pragma unroll
    for (int n = 0; n < 8; ++n) rst[n][j] = fmaxf(acc[n], 0.f);
    __syncthreads();
    int warp = j >> 5, lane = j & 31;
#pragma unroll
    for (int t = 0; t < 2; ++t) {
        int n = warp * 2 + t;
        float s = 0.f, s2 = 0.f;
#pragma unroll
        for (int c = lane; c < DOUT; c += 32) { float v = rst[n][c]; s += v; s2 += v * v; }
#pragma unroll
        for (int o = 16; o > 0; o >>= 1) {
            s  += __shfl_xor_sync(0xffffffffu, s, o);
            s2 += __shfl_xor_sync(0xffffffffu, s2, o);
        }
        float mu   = s * (1.f / DOUT);
        float var  = s2 * (1.f / DOUT) - mu * mu;
        float rstd = rsqrtf(var + 1e-5f);
#pragma unroll
        for (int c = lane; c < DOUT; c += 32) {
            out[(size_t)(node0 + n) * DOUT + c] =
                (rst[n][c] - mu) * rstd * ln_g[c] + ln_b[c];
        }
    }
}

// ---------------- launch ----------------
extern "C" void kernel_launch(void* const* d_in, const int* in_sizes, int n_in,
                              void* d_out, int out_size) {
    int base = (in_sizes[4] == 1) ? 5 : 4;   // skip scalar num_dst if present
    const float* h        = (const float*)d_in[0];
    const float* ef       = (const float*)d_in[1];
    const float* dt       = (const float*)d_in[2];
    const int*   dst_idx  = (const int*)  d_in[3];
    const float* time_w   = (const float*)d_in[base + 0];
    const float* time_b   = (const float*)d_in[base + 1];
    const float* wq       = (const float*)d_in[base + 2];
    const float* bq       = (const float*)d_in[base + 3];
    const float* wk       = (const float*)d_in[base + 4];
    const float* bk       = (const float*)d_in[base + 5];
    const float* wv       = (const float*)d_in[base + 6];
    const float* bv       = (const float*)d_in[base + 7];
    const float* att_bias = (const float*)d_in[base + 8];
    const float* wout     = (const float*)d_in[base + 9];
    const float* bout     = (const float*)d_in[base + 10];
    const float* ln_g     = (const float*)d_in[base + 11];
    const float* ln_b     = (const float*)d_in[base + 12];
    float* out = (float*)d_out;

    k_init   <<<(NUM_DST + 255) / 256, 256>>>(att_bias);
    k_qnodes <<<NUM_DST / 8, 128>>>(h, time_b, wq, bq);
    k_qb     <<<(NUM_DST * 2 + 3) / 4, 128>>>(bk);
    k_u      <<<dim3(NUM_DST / 8, 3), 128>>>(wk);
    k_hist   <<<(NUM_EDGES + 255) / 256, 256>>>(dst_idx);
    k_scan   <<<1, 1024>>>();
    k_scatter<<<(NUM_EDGES + 255) / 256, 256>>>(dst_idx);
    k_fused  <<<NUM_DST, 128>>>(h, ef, dt, time_w, time_b);
    k_sv     <<<NUM_DST / 8, 128>>>(wv, bv);
    k_out    <<<NUM_DST / 8, 128>>>(h, wout, bout, ln_g, ln_b, out);
}

// round 7
// speedup vs baseline: 19.8609x; 1.3343x over previous
#include <cuda_runtime.h>
#include <math.h>

#define NUM_DST   10000
#define NUM_EDGES 600000
#define DN  100
#define DE  172
#define DT_ 100
#define FPH 372      // features per edge = DN+DE+DT
#define DOUT 128
#define UPD 744      // 2 heads * 372

// ---------------- scratch ----------------
__device__ float g_Q[NUM_DST * DOUT];
__device__ float g_qc[NUM_DST * 2];            // Q_h . bk_h
__device__ float g_u[(size_t)NUM_DST * UPD];   // wk_h @ Q_h per dst
__device__ float g_S[(size_t)NUM_DST * UPD];   // att-weighted feature sums
__device__ float g_attsum[NUM_DST * 2];        // 1 if deg>0 else 0
__device__ float g_agg[NUM_DST * DOUT];
__device__ float g_ab[2];                      // per-head sum of att_bias
__device__ int   g_hist[NUM_DST];
__device__ int   g_rowptr[NUM_DST + 1];
__device__ int   g_cursor[NUM_DST];
__device__ int   g_csr[NUM_EDGES];

// ---------------- init: zero hist + att_bias head sums ----------------
__global__ void k_init(const float* __restrict__ att_bias) {
    int i = blockIdx.x * blockDim.x + threadIdx.x;
    if (i < NUM_DST) g_hist[i] = 0;
    if (i < 2) {
        float s = 0.f;
        for (int d = 0; d < 64; ++d) s += att_bias[i * 64 + d];
        g_ab[i] = s;
    }
}

// ---------------- Q = [h_dst | cos(time_b)] @ wq + bq ----------------
__global__ void k_qnodes(const float* __restrict__ h, const float* __restrict__ time_b,
                         const float* __restrict__ wq, const float* __restrict__ bq) {
    __shared__ float xs[8][DN];
    __shared__ float costb[DT_];
    int node0 = blockIdx.x * 8;
    int j = threadIdx.x;                       // 0..127 = output col
    if (j < DT_) costb[j] = cosf(time_b[j]);
    for (int idx = j; idx < 8 * DN; idx += 128) {
        int n = idx / DN, i = idx % DN;
        xs[n][i] = h[(node0 + n) * DN + i];
    }
    __syncthreads();
    float cacc = bq[j];
    for (int i = 0; i < DT_; ++i) cacc += costb[i] * wq[(DN + i) * DOUT + j];
    float acc[8];
#pragma unroll
    for (int n = 0; n < 8; ++n) acc[n] = cacc;
    for (int i = 0; i < DN; ++i) {
        float w = wq[i * DOUT + j];
#pragma unroll
        for (int n = 0; n < 8; ++n) acc[n] = fmaf(xs[n][i], w, acc[n]);
    }
#pragma unroll
    for (int n = 0; n < 8; ++n) g_Q[(node0 + n) * DOUT + j] = acc[n];
}

// ---------------- qc[dst][h] = Q_h[dst] . bk_h ----------------
__global__ void k_qb(const float* __restrict__ bk) {
    int idx  = blockIdx.x * 4 + (threadIdx.x >> 5);
    int lane = threadIdx.x & 31;
    if (idx >= NUM_DST * 2) return;
    int dst = idx >> 1, hh = idx & 1;
    const float* q = &g_Q[dst * DOUT + hh * 64];
    const float* b = &bk[hh * 64];
    float v = q[lane] * b[lane] + q[lane + 32] * b[lane + 32];
#pragma unroll
    for (int off = 16; off > 0; off >>= 1) v += __shfl_xor_sync(0xffffffffu, v, off);
    if (lane == 0) g_qc[idx] = v;
}

// ---------------- u = Q_h @ wk_h^T  (register-blocked smem GEMM) ----------------
// block: 256 threads, tile 32 dst x 128 i x 2 heads; microtile 4x4x2.
#define UT_DST 32
#define UT_I   128
__global__ void __launch_bounds__(256) k_u(const float* __restrict__ wk) {
    __shared__ float Qs[UT_DST][DOUT];        // 16 KB
    __shared__ float WtT[DOUT][UT_I + 4];     // [col][i], ~67.6 KB
    const int tid = threadIdx.x;
    const int d0  = blockIdx.x * UT_DST;
    const int i0  = blockIdx.y * UT_I;

    for (int idx = tid; idx < UT_DST * DOUT; idx += 256) {
        int n = idx >> 7, c = idx & 127;
        int dst = d0 + n;
        Qs[n][c] = (dst < NUM_DST) ? g_Q[dst * DOUT + c] : 0.f;
    }
    // wk tile transposed: coalesced global read (consecutive tid -> consecutive col)
    for (int idx = tid; idx < UT_I * DOUT; idx += 256) {
        int i = idx >> 7, c = idx & 127;
        int gi = i0 + i;
        WtT[c][i] = (gi < FPH) ? wk[gi * DOUT + c] : 0.f;
    }
    __syncthreads();

    const int dg = tid >> 5;       // 0..7 -> dsts d0 + dg*4 .. +3  (warp-uniform)
    const int ig = tid & 31;       // i = i0 + ig*4 .. +3
    float a0[4][4], a1[4][4];
#pragma unroll
    for (int n = 0; n < 4; ++n)
#pragma unroll
        for (int k = 0; k < 4; ++k) { a0[n][k] = 0.f; a1[n][k] = 0.f; }

#pragma unroll 4
    for (int d = 0; d < 64; ++d) {
        float4 w0 = *(const float4*)&WtT[d][ig * 4];        // head0 weights
        float4 w1 = *(const float4*)&WtT[64 + d][ig * 4];   // head1 weights
#pragma unroll
        for (int n = 0; n < 4; ++n) {
            float q0 = Qs[dg * 4 + n][d];        // broadcast
            float q1 = Qs[dg * 4 + n][64 + d];   // broadcast
            a0[n][0] = fmaf(q0, w0.x, a0[n][0]);
            a0[n][1] = fmaf(q0, w0.y, a0[n][1]);
            a0[n][2] = fmaf(q0, w0.z, a0[n][2]);
            a0[n][3] = fmaf(q0, w0.w, a0[n][3]);
            a1[n][0] = fmaf(q1, w1.x, a1[n][0]);
            a1[n][1] = fmaf(q1, w1.y, a1[n][1]);
            a1[n][2] = fmaf(q1, w1.z, a1[n][2]);
            a1[n][3] = fmaf(q1, w1.w, a1[n][3]);
        }
    }

    int i = i0 + ig * 4;
    if (i < FPH) {   // FPH % 4 == 0, so a valid start implies a full float4
#pragma unroll
        for (int n = 0; n < 4; ++n) {
            int dst = d0 + dg * 4 + n;
            if (dst < NUM_DST) {
                *(float4*)&g_u[(size_t)dst * UPD + i] =
                    make_float4(a0[n][0], a0[n][1], a0[n][2], a0[n][3]);
                *(float4*)&g_u[(size_t)dst * UPD + FPH + i] =
                    make_float4(a1[n][0], a1[n][1], a1[n][2], a1[n][3]);
            }
        }
    }
}

// ---------------- CSR build ----------------
__global__ void k_hist(const int* __restrict__ dst_idx) {
    int e = blockIdx.x * blockDim.x + threadIdx.x;
    if (e < NUM_EDGES) atomicAdd(&g_hist[dst_idx[e]], 1);
}

__global__ void k_scan() {      // single block, 1024 threads, 10 dsts/thread
    __shared__ int wsum[32];
    int t = threadIdx.x, lane = t & 31, wid = t >> 5;
    int base = t * 10;
    int loc[10]; int s = 0;
#pragma unroll
    for (int r = 0; r < 10; ++r) {
        int i = base + r;
        int c = (i < NUM_DST) ? g_hist[i] : 0;
        loc[r] = s; s += c;
    }
    int v = s;
#pragma unroll
    for (int off = 1; off < 32; off <<= 1) {
        int n = __shfl_up_sync(0xffffffffu, v, off);
        if (lane >= off) v += n;
    }
    if (lane == 31) wsum[wid] = v;
    __syncthreads();
    if (wid == 0) {
        int wv = wsum[lane];
#pragma unroll
        for (int off = 1; off < 32; off <<= 1) {
            int n = __shfl_up_sync(0xffffffffu, wv, off);
            if (lane >= off) wv += n;
        }
        wsum[lane] = wv;   // inclusive scan of warp totals
    }
    __syncthreads();
    int warpbase = (wid == 0) ? 0 : wsum[wid - 1];
    int tbase = warpbase + (v - s);   // exclusive prefix for this thread
#pragma unroll
    for (int r = 0; r < 10; ++r) {
        int i = base + r;
        if (i < NUM_DST) { int p = tbase + loc[r]; g_rowptr[i] = p; g_cursor[i] = p; }
    }
    if (t == 0) g_rowptr[NUM_DST] = NUM_EDGES;
}

__global__ void k_scatter(const int* __restrict__ dst_idx) {
    int e = blockIdx.x * blockDim.x + threadIdx.x;
    if (e >= NUM_EDGES) return;
    int pos = atomicAdd(&g_cursor[dst_idx[e]], 1);
    g_csr[pos] = e;
}

// ---------------- fused: scores + segment softmax + weighted feature sum ----------------
// one block (128 thr, 4 warps) per dst; warp-level online softmax, merged at end.
__global__ void __launch_bounds__(128) k_fused(
    const float* __restrict__ h,  const float* __restrict__ ef,
    const float* __restrict__ dtp,
    const float* __restrict__ time_w, const float* __restrict__ time_b) {
    __shared__ float tw[DT_], tb[DT_];
    __shared__ float Ss[4][UPD];
    __shared__ float sm_m[4][2], sm_z[4][2];
    int dst  = blockIdx.x;
    int tid  = threadIdx.x, lane = tid & 31, warp = tid >> 5;
    int start = g_rowptr[dst], end = g_rowptr[dst + 1];
    if (start == end) {      // empty segment
        for (int idx = tid; idx < UPD; idx += 128) g_S[(size_t)dst * UPD + idx] = 0.f;
        if (tid < 2) g_attsum[dst * 2 + tid] = 0.f;
        return;
    }
    if (tid < DT_) { tw[tid] = time_w[tid]; tb[tid] = time_b[tid]; }

    float ur0[12], ur1[12];
#pragma unroll
    for (int k = 0; k < 12; ++k) {
        int f = lane + 32 * k;
        ur0[k] = (f < FPH) ? g_u[(size_t)dst * UPD + f]       : 0.f;
        ur1[k] = (f < FPH) ? g_u[(size_t)dst * UPD + FPH + f] : 0.f;
    }
    float c0 = g_qc[dst * 2 + 0] + g_ab[0];
    float c1 = g_qc[dst * 2 + 1] + g_ab[1];
    __syncthreads();

    float m0 = -1e30f, m1 = -1e30f, z0 = 0.f, z1 = 0.f;
    float S0[12], S1[12];
#pragma unroll
    for (int k = 0; k < 12; ++k) { S0[k] = 0.f; S1[k] = 0.f; }

    for (int pos = start + warp; pos < end; pos += 4) {
        int   eid = g_csr[pos];
        float dtv = dtp[eid];
        float x[12];
#pragma unroll
        for (int k = 0; k < 12; ++k) {
            int f = lane + 32 * k;
            float v;
            if (f < DN)            v = h[(size_t)(NUM_DST + eid) * DN + f];
            else if (f < DN + DE)  v = ef[(size_t)eid * DE + (f - DN)];
            else if (f < FPH) {
                int ti = f - (DN + DE);
                v = __cosf(dtv * tw[ti] + tb[ti]);
            } else v = 0.f;
            x[k] = v;
        }
        float p0 = 0.f, p1 = 0.f;
#pragma unroll
        for (int k = 0; k < 12; ++k) {
            p0 = fmaf(x[k], ur0[k], p0);
            p1 = fmaf(x[k], ur1[k], p1);
        }
#pragma unroll
        for (int off = 16; off > 0; off >>= 1) {
            p0 += __shfl_xor_sync(0xffffffffu, p0, off);
            p1 += __shfl_xor_sync(0xffffffffu, p1, off);
        }
        float s0 = p0 + c0; s0 = (s0 > 0.f) ? s0 : 0.2f * s0;  // leaky_relu
        float s1 = p1 + c1; s1 = (s1 > 0.f) ? s1 : 0.2f * s1;
        // online softmax accumulation, head 0
        if (s0 > m0) {
            float sc = __expf(m0 - s0);
            z0 = fmaf(z0, sc, 1.f);
#pragma unroll
            for (int k = 0; k < 12; ++k) S0[k] = fmaf(S0[k], sc, x[k]);
            m0 = s0;
        } else {
            float e = __expf(s0 - m0);
            z0 += e;
#pragma unroll
            for (int k = 0; k < 12; ++k) S0[k] = fmaf(e, x[k], S0[k]);
        }
        // head 1
        if (s1 > m1) {
            float sc = __expf(m1 - s1);
            z1 = fmaf(z1, sc, 1.f);
#pragma unroll
            for (int k = 0; k < 12; ++k) S1[k] = fmaf(S1[k], sc, x[k]);
            m1 = s1;
        } else {
            float e = __expf(s1 - m1);
            z1 += e;
#pragma unroll
            for (int k = 0; k < 12; ++k) S1[k] = fmaf(e, x[k], S1[k]);
        }
    }

    // merge warp partials
#pragma unroll
    for (int k = 0; k < 12; ++k) {
        int f = lane + 32 * k;
        if (f < FPH) { Ss[warp][f] = S0[k]; Ss[warp][FPH + f] = S1[k]; }
    }
    if (lane == 0) {
        sm_m[warp][0] = m0; sm_m[warp][1] = m1;
        sm_z[warp][0] = z0; sm_z[warp][1] = z1;
    }
    __syncthreads();
    float gm0 = -1e30f, gm1 = -1e30f;
#pragma unroll
    for (int w = 0; w < 4; ++w) {
        gm0 = fmaxf(gm0, sm_m[w][0]);
        gm1 = fmaxf(gm1, sm_m[w][1]);
    }
    float ew0[4], ew1[4], gz0 = 0.f, gz1 = 0.f;
#pragma unroll
    for (int w = 0; w < 4; ++w) {
        ew0[w] = __expf(sm_m[w][0] - gm0); gz0 = fmaf(sm_z[w][0], ew0[w], gz0);
        ew1[w] = __expf(sm_m[w][1] - gm1); gz1 = fmaf(sm_z[w][1], ew1[w], gz1);
    }
    float inv0 = 1.f / gz0, inv1 = 1.f / gz1;
    for (int f = tid; f < FPH; f += 128) {
        float a0 = 0.f, a1 = 0.f;
#pragma unroll
        for (int w = 0; w < 4; ++w) {
            a0 = fmaf(Ss[w][f],       ew0[w], a0);
            a1 = fmaf(Ss[w][FPH + f], ew1[w], a1);
        }
        g_S[(size_t)dst * UPD + f]       = a0 * inv0;
        g_S[(size_t)dst * UPD + FPH + f] = a1 * inv1;
    }
    if (tid < 2) g_attsum[dst * 2 + tid] = 1.f;
}

// ---------------- agg[dst,c] = S_h(c)[dst] . wv[:,c] + bv_c * attsum ----------------
__global__ void k_sv(const float* __restrict__ wv, const float* __restrict__ bv) {
    __shared__ float Ssm[8][UPD];
    __shared__ float asum[8][2];
    int n0 = blockIdx.x * 8;
    int j  = threadIdx.x;                       // 0..127 = output col
    for (int idx = j; idx < 8 * UPD; idx += 128) {
        int n = idx / UPD, i = idx % UPD;
        Ssm[n][i] = g_S[(size_t)(n0 + n) * UPD + i];
    }
    if (j < 16) asum[j >> 1][j & 1] = g_attsum[(n0 + (j >> 1)) * 2 + (j & 1)];
    __syncthreads();
    int hh = j >> 6;
    float bvj = bv[j];
    float acc[8];
#pragma unroll
    for (int n = 0; n < 8; ++n) acc[n] = bvj * asum[n][hh];
    for (int i = 0; i < FPH; ++i) {
        float w = wv[i * DOUT + j];
#pragma unroll
        for (int n = 0; n < 8; ++n) acc[n] = fmaf(Ssm[n][hh * FPH + i], w, acc[n]);
    }
#pragma unroll
    for (int n = 0; n < 8; ++n) g_agg[(n0 + n) * DOUT + j] = acc[n];
}

// ---------------- out = LN(relu([agg | h_dst] @ wout + bout)) ----------------
__global__ void k_out(const float* __restrict__ h, const float* __restrict__ wout,
                      const float* __restrict__ bout, const float* __restrict__ ln_g,
                      const float* __restrict__ ln_b, float* __restrict__ out) {
    __shared__ float xs[8][DOUT + DN];
    __shared__ float rst[8][DOUT];
    int node0 = blockIdx.x * 8;
    int j = threadIdx.x;
    for (int idx = j; idx < 8 * DOUT; idx += 128) {
        int n = idx >> 7, i = idx & 127;
        xs[n][i] = g_agg[(node0 + n) * DOUT + i];
    }
    for (int idx = j; idx < 8 * DN; idx += 128) {
        int n = idx / DN, i = idx % DN;
        xs[n][DOUT + i] = h[(node0 + n) * DN + i];
    }
    __syncthreads();
    float b0 = bout[j];
    float acc[8];
#pragma unroll
    for (int n = 0; n < 8; ++n) acc[n] = b0;
    for (int i = 0; i < DOUT + DN; ++i) {
        float w = wout[i * DOUT + j];
#pragma unroll
        for (int n = 0; n < 8; ++n) acc[n] = fmaf(xs[n][i], w, acc[n]);
    }
#pragma unroll
    for (int n = 0; n < 8; ++n) rst[n][j] = fmaxf(acc[n], 0.f);
    __syncthreads();
    int warp = j >> 5, lane = j & 31;
#pragma unroll
    for (int t = 0; t < 2; ++t) {
        int n = warp * 2 + t;
        float s = 0.f, s2 = 0.f;
#pragma unroll
        for (int c = lane; c < DOUT; c += 32) { float v = rst[n][c]; s += v; s2 += v * v; }
#pragma unroll
        for (int o = 16; o > 0; o >>= 1) {
            s  += __shfl_xor_sync(0xffffffffu, s, o);
            s2 += __shfl_xor_sync(0xffffffffu, s2, o);
        }
        float mu   = s * (1.f / DOUT);
        float var  = s2 * (1.f / DOUT) - mu * mu;
        float rstd = rsqrtf(var + 1e-5f);
#pragma unroll
        for (int c = lane; c < DOUT; c += 32) {
            out[(size_t)(node0 + n) * DOUT + c] =
                (rst[n][c] - mu) * rstd * ln_g[c] + ln_b[c];
        }
    }
}

// ---------------- launch ----------------
extern "C" void kernel_launch(void* const* d_in, const int* in_sizes, int n_in,
                              void* d_out, int out_size) {
    int base = (in_sizes[4] == 1) ? 5 : 4;   // skip scalar num_dst if present
    const float* h        = (const float*)d_in[0];
    const float* ef       = (const float*)d_in[1];
    const float* dt       = (const float*)d_in[2];
    const int*   dst_idx  = (const int*)  d_in[3];
    const float* time_w   = (const float*)d_in[base + 0];
    const float* time_b   = (const float*)d_in[base + 1];
    const float* wq       = (const float*)d_in[base + 2];
    const float* bq       = (const float*)d_in[base + 3];
    const float* wk       = (const float*)d_in[base + 4];
    const float* bk       = (const float*)d_in[base + 5];
    const float* wv       = (const float*)d_in[base + 6];
    const float* bv       = (const float*)d_in[base + 7];
    const float* att_bias = (const float*)d_in[base + 8];
    const float* wout     = (const float*)d_in[base + 9];
    const float* bout     = (const float*)d_in[base + 10];
    const float* ln_g     = (const float*)d_in[base + 11];
    const float* ln_b     = (const float*)d_in[base + 12];
    float* out = (float*)d_out;

    k_init   <<<(NUM_DST + 255) / 256, 256>>>(att_bias);
    k_qnodes <<<NUM_DST / 8, 128>>>(h, time_b, wq, bq);
    k_qb     <<<(NUM_DST * 2 + 3) / 4, 128>>>(bk);
    k_u      <<<dim3((NUM_DST + UT_DST - 1) / UT_DST, (FPH + UT_I - 1) / UT_I), 256>>>(wk);
    k_hist   <<<(NUM_EDGES + 255) / 256, 256>>>(dst_idx);
    k_scan   <<<1, 1024>>>();
    k_scatter<<<(NUM_EDGES + 255) / 256, 256>>>(dst_idx);
    k_fused  <<<NUM_DST, 128>>>(h, ef, dt, time_w, time_b);
    k_sv     <<<NUM_DST / 8, 128>>>(wv, bv);
    k_out    <<<NUM_DST / 8, 128>>>(h, wout, bout, ln_g, ln_b, out);
}